// round 10
// baseline (speedup 1.0000x reference)
#include <cuda_runtime.h>
#include <cuda_bf16.h>
#include <math.h>
#include <stdint.h>

#define NB 8
#define BATCH 256
#define NV 14062
#define NV3 (NV*3)          // 42186
#define TPITCH 42188        // g_tt row pitch (mult of 4 for float4 loads)
#define KD 120              // 63 pose-corr + 55 bsw + 2 zero pad (T excluded)
#define NTILE 96            // comps per block = 32 vertices exactly
#define VTILE 32
#define MTILE 64            // batches per M-tile iteration
#define NBLKS ((NV3 + NTILE - 1) / NTILE)   // 440

#define SB_WORDS (15*12*66)          // 11880 (full-K B frags)
#define SB_BYTES (SB_WORDS*4)        // 47520

// scratch (allocation-free requirement -> device globals)
__device__ __align__(16) uint32_t g_coefA[BATCH * KD];   // tf32 bits, A-fragment order
__device__ __align__(16) float    g_bone[BATCH * NB * 12];
__device__ __align__(16) float    g_tt[(size_t)BATCH * TPITCH + 4];  // GEMM out

struct Aff { float r[9]; float t[3]; };

__device__ __forceinline__ Aff amul(const Aff& A, const Aff& B) {
    Aff C;
#pragma unroll
    for (int i = 0; i < 3; i++) {
#pragma unroll
        for (int j = 0; j < 3; j++)
            C.r[i*3+j] = A.r[i*3+0]*B.r[0*3+j] + A.r[i*3+1]*B.r[1*3+j] + A.r[i*3+2]*B.r[2*3+j];
        C.t[i] = A.r[i*3+0]*B.t[0] + A.r[i*3+1]*B.t[1] + A.r[i*3+2]*B.t[2] + A.t[i];
    }
    return C;
}

__device__ __forceinline__ Aff ainv_rigid(const Aff& A) {
    Aff C;
#pragma unroll
    for (int i = 0; i < 3; i++)
#pragma unroll
        for (int j = 0; j < 3; j++)
            C.r[i*3+j] = A.r[j*3+i];
#pragma unroll
    for (int i = 0; i < 3; i++)
        C.t[i] = -(C.r[i*3+0]*A.t[0] + C.r[i*3+1]*A.t[1] + C.r[i*3+2]*A.t[2]);
    return C;
}

__device__ __forceinline__ void rodrigues(const float* rv, float* R) {
    float x = rv[0], y = rv[1], z = rv[2];
    float d = x*x + y*y + z*z + 1e-12f;
    float ang = sqrtf(d);
    float inv = 1.0f / ang;
    float kx = x*inv, ky = y*inv, kz = z*inv;
    float s = sinf(ang), c = cosf(ang);
    float kk = kx*kx + ky*ky + kz*kz;
    float oc = 1.0f - c;
    R[0] = 1.0f + oc*(kx*kx - kk);
    R[1] = -s*kz + oc*(kx*ky);
    R[2] =  s*ky + oc*(kx*kz);
    R[3] =  s*kz + oc*(ky*kx);
    R[4] = 1.0f + oc*(ky*ky - kk);
    R[5] = -s*kx + oc*(ky*kz);
    R[6] = -s*ky + oc*(kz*kx);
    R[7] =  s*kx + oc*(kz*ky);
    R[8] = 1.0f + oc*(kz*kz - kk);
}

__device__ __forceinline__ uint32_t to_tf32(float f) {
    uint32_t u;
    asm("cvt.rna.tf32.f32 %0, %1;" : "=r"(u) : "f"(f));
    return u;
}

// write coef value k for batch b into m16n8k8 A-fragment-ordered g_coefA
__device__ __forceinline__ void store_coef(int b, int k, float v) {
    int b64  = b >> 6;
    int mblk = (b >> 4) & 3;
    int r    = b & 15;
    int g    = r & 7;
    int hi   = r >> 3;
    int k8 = k >> 3, t = k & 7, tig = t & 3, j2 = t >> 2;
    int lane = g*4 + tig;
    int reg  = j2*2 + hi;
    g_coefA[(((b64*15 + k8)*4 + mblk)*32 + lane)*4 + reg] = to_tf32(v);
}

// Merged prep: one block per batch.
__global__ void prep_kernel(const float* __restrict__ theta,
                            const float* __restrict__ bsw,
                            const float* __restrict__ L2P) {
    __shared__ float sR[NB * 9];
    const int b = blockIdx.x;
    const int t = threadIdx.x;
    if (t < 8) {
        float R[9];
        rodrigues(theta + (b*NB + t)*3, R);
#pragma unroll
        for (int i = 0; i < 9; i++) sR[t*9 + i] = R[i];
        if (t >= 1) {
#pragma unroll
            for (int i = 0; i < 3; i++)
#pragma unroll
                for (int j = 0; j < 3; j++)
                    store_coef(b, (t-1)*9 + i*3 + j, R[i*3+j] - (i == j ? 1.0f : 0.0f));
        }
    } else if (t < 63) {
        int j = t - 8;
        store_coef(b, 63 + j, bsw[b*55 + j]);
    }
    __syncthreads();

    if (t == 0) {
        Aff M, rest;
#pragma unroll
        for (int n = 0; n < NB; n++) {
            Aff l2p;
#pragma unroll
            for (int i = 0; i < 3; i++) {
#pragma unroll
                for (int j = 0; j < 3; j++) l2p.r[i*3+j] = L2P[n*16 + i*4 + j];
                l2p.t[i] = L2P[n*16 + i*4 + 3];
            }
            Aff loc;
#pragma unroll
            for (int i = 0; i < 9; i++) loc.r[i] = sR[n*9 + i];
            loc.t[0] = loc.t[1] = loc.t[2] = 0.0f;

            Aff An = amul(l2p, loc);
            M    = (n == 0) ? An  : amul(M, An);
            rest = (n == 0) ? l2p : amul(rest, l2p);

            Aff w2l = ainv_rigid(rest);
            Aff G = amul(M, w2l);

            float* gp = g_bone + b*(NB*12) + n*12;
#pragma unroll
            for (int i = 0; i < 3; i++) {
                gp[i*4+0] = G.r[i*3+0];
                gp[i*4+1] = G.r[i*3+1];
                gp[i*4+2] = G.r[i*3+2];
                gp[i*4+3] = G.t[i];
            }
        }
    }
}

// tf32 GEMM only: g_tt[b][c] = sum_k coef[b][k]*Basis[k][c]. B-stationary,
// no epilogue, no staging -> small register set, 3 CTAs/SM, no syncthreads
// in the M-loop. C fragments stored straight to g_tt (32B segments).
__global__ __launch_bounds__(256, 3)
void gemm_kernel(const float* __restrict__ P,
                 const float* __restrict__ E) {
    extern __shared__ __align__(16) uint32_t sB[];

    const int tid   = threadIdx.x;
    const int lane  = tid & 31;
    const int wid   = tid >> 5;
    const int warpM = wid >> 2;      // 0..1
    const int warpN = wid & 3;       // 0..3
    const int cbase = blockIdx.x * NTILE;

    // fill full-K B tile [120 x 96] in fragment order (once)
    for (int idx = tid; idx < KD*NTILE; idx += 256) {
        int kl = idx / NTILE;
        int cl = idx - kl*NTILE;
        int c  = cbase + cl;
        float v = 0.0f;
        if (c < NV3) {
            if (kl < 63)       v = P[(size_t)(kl+9)*NV3 + c];
            else if (kl < 118) v = E[(size_t)(kl-63)*NV3 + c];
        }
        int k8 = kl >> 3, t = kl & 7, tig = t & 3, j = t >> 2;
        int nblk = cl >> 3, gg = cl & 7;
        sB[k8*(12*66) + nblk*66 + (gg*4 + tig)*2 + j] = to_tf32(v);
    }
    __syncthreads();

    const int ggr = lane >> 2;
    const int tt4 = lane & 3;

    for (int mt = 0; mt < 4; mt++) {
        const uint32_t* Ag = g_coefA + mt*(MTILE*KD);
        const int Mbase = mt * MTILE;

        float acc[2][3][4];
#pragma unroll
        for (int mi = 0; mi < 2; mi++)
#pragma unroll
            for (int ni = 0; ni < 3; ni++)
#pragma unroll
                for (int qq = 0; qq < 4; qq++) acc[mi][ni][qq] = 0.0f;

#pragma unroll
        for (int k8 = 0; k8 < 15; k8++) {
            uint32_t a[2][4];
#pragma unroll
            for (int mi = 0; mi < 2; mi++) {
                uint4 av = *(const uint4*)&Ag[((k8*4 + warpM*2 + mi)*32 + lane)*4];
                a[mi][0] = av.x; a[mi][1] = av.y; a[mi][2] = av.z; a[mi][3] = av.w;
            }
            uint32_t bf[3][2];
#pragma unroll
            for (int ni = 0; ni < 3; ni++) {
                uint2 bv = *(const uint2*)&sB[k8*(12*66) + (warpN*3 + ni)*66 + lane*2];
                bf[ni][0] = bv.x; bf[ni][1] = bv.y;
            }
#pragma unroll
            for (int mi = 0; mi < 2; mi++)
#pragma unroll
                for (int ni = 0; ni < 3; ni++) {
                    asm volatile(
                        "mma.sync.aligned.m16n8k8.row.col.f32.tf32.tf32.f32 "
                        "{%0,%1,%2,%3}, {%4,%5,%6,%7}, {%8,%9}, {%0,%1,%2,%3};"
                        : "+f"(acc[mi][ni][0]), "+f"(acc[mi][ni][1]),
                          "+f"(acc[mi][ni][2]), "+f"(acc[mi][ni][3])
                        : "r"(a[mi][0]), "r"(a[mi][1]), "r"(a[mi][2]), "r"(a[mi][3]),
                          "r"(bf[ni][0]), "r"(bf[ni][1]));
                }
        }

        // store C fragments
#pragma unroll
        for (int mi = 0; mi < 2; mi++) {
#pragma unroll
            for (int ni = 0; ni < 3; ni++) {
                int row = Mbase + warpM*32 + mi*16 + ggr;
                int col = cbase + warpN*24 + ni*8 + tt4*2;
                if (col < NV3) {
                    *(float2*)&g_tt[(size_t)row*TPITCH + col] =
                        make_float2(acc[mi][ni][0], acc[mi][ni][1]);
                    *(float2*)&g_tt[(size_t)(row+8)*TPITCH + col] =
                        make_float2(acc[mi][ni][2], acc[mi][ni][3]);
                }
            }
        }
    }
}

// Epilogue kernel: thread owns 4 adjacent vertices x 1 batch row.
// G loads shared by 4 vertices; g_tt read = 3 LDG.128; no smem, no acc
// registers to fight -> no spills, high MLP.
// grid = (440 vert-tiles, 8 row-blocks of 32), block = 256.
__global__ __launch_bounds__(256)
void epi_kernel(const float* __restrict__ T,
                const float* __restrict__ W,
                const float* __restrict__ ts,
                const float* __restrict__ uvgrid,
                const float* __restrict__ L,
                const float* __restrict__ tau,
                const float* __restrict__ alpha,
                float* __restrict__ out) {
    const int tid = threadIdx.x;
    const int q   = tid & 7;                  // vertex quad
    const int r   = tid >> 3;                 // row 0..31
    const int b   = blockIdx.y * 32 + r;
    const int vp  = blockIdx.x * VTILE + q*4;

    bool hval[4];
#pragma unroll
    for (int u = 0; u < 4; u++) hval[u] = (vp + u) < NV;
    if (!hval[0]) return;

    const float tb = tau[b];
    const float al = alpha[b];

    // g_tt: 12 contiguous floats (aligned: vp*3 mult of 4, TPITCH mult of 4)
    const float* cp = g_tt + (size_t)b*TPITCH + (size_t)vp*3;
    float4 c0 = *(const float4*)(cp + 0);
    float4 c1 = *(const float4*)(cp + 4);
    float4 c2 = *(const float4*)(cp + 8);
    float cc[12] = {c0.x,c0.y,c0.z,c0.w, c1.x,c1.y,c1.z,c1.w,
                    c2.x,c2.y,c2.z,c2.w};

    float px[4], py[4], pz[4], ox[4], oy[4], oz[4];
#pragma unroll
    for (int u = 0; u < 4; u++) {
        const int v = hval[u] ? (vp + u) : (NV - 1);
        float ux = uvgrid[v*2+0];
        float uy = uvgrid[v*2+1];
        float x = fminf(fmaxf(ux * 255.0f, 0.0f), 255.0f);
        int x0 = (int)floorf(x);
        int x1 = min(x0 + 1, 255);
        float wx = x - (float)x0;
        float y = fminf(fmaxf((uy + tb) * 255.0f, 0.0f), 255.0f);
        int y0 = (int)floorf(y);
        int y1 = min(y0 + 1, 255);
        float wy = y - (float)y0;
        float v00 = L[y0*256 + x0], v01 = L[y0*256 + x1];
        float v10 = L[y1*256 + x0], v11 = L[y1*256 + x1];
        float dist = (v00*(1.0f-wx) + v01*wx)*(1.0f-wy)
                   + (v10*(1.0f-wx) + v11*wx)*wy;
        float s = al * dist;

        px[u] = cc[u*3+0] + T[v*3+0] + s*ts[v*3+0];
        py[u] = cc[u*3+1] + T[v*3+1] + s*ts[v*3+1];
        pz[u] = cc[u*3+2] + T[v*3+2] + s*ts[v*3+2];
        ox[u] = 0.0f; oy[u] = 0.0f; oz[u] = 0.0f;
    }

    const float4* Gb = (const float4*)(g_bone + b*(NB*12));
#pragma unroll
    for (int n = 0; n < NB; n++) {
        float4 g0 = Gb[n*3 + 0];   // shared by all 4 vertices
        float4 g1 = Gb[n*3 + 1];
        float4 g2 = Gb[n*3 + 2];
        const float* Wn = W + n*NV;
#pragma unroll
        for (int u = 0; u < 4; u++) {
            float wn = hval[u] ? Wn[vp + u] : 0.0f;
            ox[u] = fmaf(wn, fmaf(g0.x, px[u], fmaf(g0.y, py[u], fmaf(g0.z, pz[u], g0.w))), ox[u]);
            oy[u] = fmaf(wn, fmaf(g1.x, px[u], fmaf(g1.y, py[u], fmaf(g1.z, pz[u], g1.w))), oy[u]);
            oz[u] = fmaf(wn, fmaf(g2.x, px[u], fmaf(g2.y, py[u], fmaf(g2.z, pz[u], g2.w))), oz[u]);
        }
    }

    size_t base = (size_t)b * NV3 + (size_t)vp * 3;
    if (hval[3]) {
        *(float2*)&out[base +  0] = make_float2(ox[0], oy[0]);
        *(float2*)&out[base +  2] = make_float2(oz[0], ox[1]);
        *(float2*)&out[base +  4] = make_float2(oy[1], oz[1]);
        *(float2*)&out[base +  6] = make_float2(ox[2], oy[2]);
        *(float2*)&out[base +  8] = make_float2(oz[2], ox[3]);
        *(float2*)&out[base + 10] = make_float2(oy[3], oz[3]);
    } else {
#pragma unroll
        for (int u = 0; u < 4; u++) {
            if (hval[u]) {
                out[base + u*3 + 0] = ox[u];
                out[base + u*3 + 1] = oy[u];
                out[base + u*3 + 2] = oz[u];
            }
        }
    }
}

extern "C" void kernel_launch(void* const* d_in, const int* in_sizes, int n_in,
                              void* d_out, int out_size) {
    const float* theta  = (const float*)d_in[0];
    const float* tau    = (const float*)d_in[1];
    const float* alpha  = (const float*)d_in[2];
    const float* bsw    = (const float*)d_in[3];
    const float* W      = (const float*)d_in[4];
    const float* T      = (const float*)d_in[5];
    const float* P      = (const float*)d_in[6];
    const float* L      = (const float*)d_in[7];
    const float* ts     = (const float*)d_in[8];
    const float* L2P    = (const float*)d_in[9];
    const float* E      = (const float*)d_in[10];
    const float* uvgrid = (const float*)d_in[11];
    float* out = (float*)d_out;

    cudaFuncSetAttribute(gemm_kernel,
                         cudaFuncAttributeMaxDynamicSharedMemorySize, SB_BYTES);

    prep_kernel<<<BATCH, 64>>>(theta, bsw, L2P);

    gemm_kernel<<<NBLKS, 256, SB_BYTES>>>(P, E);

    dim3 egrid(NBLKS, BATCH / 32);
    epi_kernel<<<egrid, 256>>>(T, W, ts, uvgrid, L, tau, alpha, out);
}

// round 11
// speedup vs baseline: 1.0534x; 1.0534x over previous
#include <cuda_runtime.h>
#include <cuda_bf16.h>
#include <cuda_fp16.h>
#include <math.h>
#include <stdint.h>

#define NB 8
#define BATCH 256
#define NV 14062
#define NV3 (NV*3)          // 42186
#define KD 120              // 63 pose-corr + 55 bsw + 2 zero pad (T excluded)
#define NTILE 96            // comps per block = 32 vertices exactly
#define VTILE 32
#define MTILE 64            // batches per M-tile iteration
#define NBLKS ((NV3 + NTILE - 1) / NTILE)   // 440
#define ST_PITCH 104        // staging row pitch in halves (conflict-free drain)

#define SB_WORDS (15*12*66)                  // 11880 (full-K B frags)
#define ST_BYTES (MTILE*ST_PITCH*2)          // 13312 (fp16 staging)
#define SMEM_BYTES (SB_WORDS*4 + ST_BYTES)   // 60832

// scratch (allocation-free requirement -> device globals)
__device__ __align__(16) uint32_t g_coefA[BATCH * KD];   // tf32 bits, A-fragment order
__device__ __align__(16) float    g_bone[BATCH * NB * 12];

struct Aff { float r[9]; float t[3]; };

__device__ __forceinline__ Aff amul(const Aff& A, const Aff& B) {
    Aff C;
#pragma unroll
    for (int i = 0; i < 3; i++) {
#pragma unroll
        for (int j = 0; j < 3; j++)
            C.r[i*3+j] = A.r[i*3+0]*B.r[0*3+j] + A.r[i*3+1]*B.r[1*3+j] + A.r[i*3+2]*B.r[2*3+j];
        C.t[i] = A.r[i*3+0]*B.t[0] + A.r[i*3+1]*B.t[1] + A.r[i*3+2]*B.t[2] + A.t[i];
    }
    return C;
}

__device__ __forceinline__ Aff ainv_rigid(const Aff& A) {
    Aff C;
#pragma unroll
    for (int i = 0; i < 3; i++)
#pragma unroll
        for (int j = 0; j < 3; j++)
            C.r[i*3+j] = A.r[j*3+i];
#pragma unroll
    for (int i = 0; i < 3; i++)
        C.t[i] = -(C.r[i*3+0]*A.t[0] + C.r[i*3+1]*A.t[1] + C.r[i*3+2]*A.t[2]);
    return C;
}

__device__ __forceinline__ void rodrigues(const float* rv, float* R) {
    float x = rv[0], y = rv[1], z = rv[2];
    float d = x*x + y*y + z*z + 1e-12f;
    float ang = sqrtf(d);
    float inv = 1.0f / ang;
    float kx = x*inv, ky = y*inv, kz = z*inv;
    float s = sinf(ang), c = cosf(ang);
    float kk = kx*kx + ky*ky + kz*kz;
    float oc = 1.0f - c;
    R[0] = 1.0f + oc*(kx*kx - kk);
    R[1] = -s*kz + oc*(kx*ky);
    R[2] =  s*ky + oc*(kx*kz);
    R[3] =  s*kz + oc*(ky*kx);
    R[4] = 1.0f + oc*(ky*ky - kk);
    R[5] = -s*kx + oc*(ky*kz);
    R[6] = -s*ky + oc*(kz*kx);
    R[7] =  s*kx + oc*(kz*ky);
    R[8] = 1.0f + oc*(kz*kz - kk);
}

__device__ __forceinline__ uint32_t to_tf32(float f) {
    uint32_t u;
    asm("cvt.rna.tf32.f32 %0, %1;" : "=r"(u) : "f"(f));
    return u;
}

// write coef value k for batch b into m16n8k8 A-fragment-ordered g_coefA
__device__ __forceinline__ void store_coef(int b, int k, float v) {
    int b64  = b >> 6;
    int mblk = (b >> 4) & 3;
    int r    = b & 15;
    int g    = r & 7;
    int hi   = r >> 3;
    int k8 = k >> 3, t = k & 7, tig = t & 3, j2 = t >> 2;
    int lane = g*4 + tig;
    int reg  = j2*2 + hi;
    g_coefA[(((b64*15 + k8)*4 + mblk)*32 + lane)*4 + reg] = to_tf32(v);
}

// Merged prep: one block per batch.
__global__ void prep_kernel(const float* __restrict__ theta,
                            const float* __restrict__ bsw,
                            const float* __restrict__ L2P) {
    __shared__ float sR[NB * 9];
    const int b = blockIdx.x;
    const int t = threadIdx.x;
    if (t < 8) {
        float R[9];
        rodrigues(theta + (b*NB + t)*3, R);
#pragma unroll
        for (int i = 0; i < 9; i++) sR[t*9 + i] = R[i];
        if (t >= 1) {
#pragma unroll
            for (int i = 0; i < 3; i++)
#pragma unroll
                for (int j = 0; j < 3; j++)
                    store_coef(b, (t-1)*9 + i*3 + j, R[i*3+j] - (i == j ? 1.0f : 0.0f));
        }
    } else if (t < 63) {
        int j = t - 8;
        store_coef(b, 63 + j, bsw[b*55 + j]);
    }
    __syncthreads();

    if (t == 0) {
        Aff M, rest;
#pragma unroll
        for (int n = 0; n < NB; n++) {
            Aff l2p;
#pragma unroll
            for (int i = 0; i < 3; i++) {
#pragma unroll
                for (int j = 0; j < 3; j++) l2p.r[i*3+j] = L2P[n*16 + i*4 + j];
                l2p.t[i] = L2P[n*16 + i*4 + 3];
            }
            Aff loc;
#pragma unroll
            for (int i = 0; i < 9; i++) loc.r[i] = sR[n*9 + i];
            loc.t[0] = loc.t[1] = loc.t[2] = 0.0f;

            Aff An = amul(l2p, loc);
            M    = (n == 0) ? An  : amul(M, An);
            rest = (n == 0) ? l2p : amul(rest, l2p);

            Aff w2l = ainv_rigid(rest);
            Aff G = amul(M, w2l);

            float* gp = g_bone + b*(NB*12) + n*12;
#pragma unroll
            for (int i = 0; i < 3; i++) {
                gp[i*4+0] = G.r[i*3+0];
                gp[i*4+1] = G.r[i*3+1];
                gp[i*4+2] = G.r[i*3+2];
                gp[i*4+3] = G.t[i];
            }
        }
    }
}

// Fused tf32 GEMM + epilogue, B-stationary, 3 CTAs/SM.
// fp16 C staging (13.3KB) keeps total smem at 60.8KB so 3 blocks fit per SM;
// __launch_bounds__(256,3) caps regs at 85. Epilogue: 2 verts x 4 rows per
// thread (G loads shared by 2 verts), per-vertex state reloaded per M-tile
// AFTER acc drain so it never coexists with MMA accumulators.
__global__ __launch_bounds__(256, 3)
void fused_kernel(const float* __restrict__ P,
                  const float* __restrict__ E,
                  const float* __restrict__ T,
                  const float* __restrict__ W,
                  const float* __restrict__ ts,
                  const float* __restrict__ uvgrid,
                  const float* __restrict__ L,
                  const float* __restrict__ tau,
                  const float* __restrict__ alpha,
                  float* __restrict__ out) {
    extern __shared__ __align__(16) char smem_raw[];
    uint32_t* sB = (uint32_t*)smem_raw;
    __half*   st = (__half*)(sB + SB_WORDS);

    const int tid   = threadIdx.x;
    const int lane  = tid & 31;
    const int wid   = tid >> 5;
    const int warpM = wid >> 2;      // 0..1
    const int warpN = wid & 3;       // 0..3
    const int cbase = blockIdx.x * NTILE;
    const int vbase = blockIdx.x * VTILE;

    // ---- fill full-K B tile [120 x 96] in fragment order (once) ----
    for (int idx = tid; idx < KD*NTILE; idx += 256) {
        int kl = idx / NTILE;            // 0..119
        int cl = idx - kl*NTILE;         // 0..95
        int c  = cbase + cl;
        float v = 0.0f;
        if (c < NV3) {
            if (kl < 63)       v = P[(size_t)(kl+9)*NV3 + c];
            else if (kl < 118) v = E[(size_t)(kl-63)*NV3 + c];
        }
        int k8 = kl >> 3, t = kl & 7, tig = t & 3, j = t >> 2;
        int nblk = cl >> 3, gg = cl & 7;
        sB[k8*(12*66) + nblk*66 + (gg*4 + tig)*2 + j] = to_tf32(v);
    }

    // epilogue thread mapping: 2 adjacent vertices x 4 rows
    const int vl2  = tid & 15;          // vertex-pair id
    const int rgrp = tid >> 4;          // row group 0..15
    const int vp   = vbase + vl2*2;     // even; NV even -> pair valid together
    const bool valid = (vp < NV);

    __syncthreads();

    // ---- M-tile loop ----
    for (int mt = 0; mt < 4; mt++) {
        const uint32_t* Ag = g_coefA + mt*(MTILE*KD);
        const int Mbase = mt * MTILE;

        float acc[2][3][4];
#pragma unroll
        for (int mi = 0; mi < 2; mi++)
#pragma unroll
            for (int ni = 0; ni < 3; ni++)
#pragma unroll
                for (int qq = 0; qq < 4; qq++) acc[mi][ni][qq] = 0.0f;

#pragma unroll
        for (int k8 = 0; k8 < 15; k8++) {
            uint32_t a[2][4];
#pragma unroll
            for (int mi = 0; mi < 2; mi++) {
                uint4 av = *(const uint4*)&Ag[((k8*4 + warpM*2 + mi)*32 + lane)*4];
                a[mi][0] = av.x; a[mi][1] = av.y; a[mi][2] = av.z; a[mi][3] = av.w;
            }
            uint32_t bf[3][2];
#pragma unroll
            for (int ni = 0; ni < 3; ni++) {
                uint2 bv = *(const uint2*)&sB[k8*(12*66) + (warpN*3 + ni)*66 + lane*2];
                bf[ni][0] = bv.x; bf[ni][1] = bv.y;
            }
#pragma unroll
            for (int mi = 0; mi < 2; mi++)
#pragma unroll
                for (int ni = 0; ni < 3; ni++) {
                    asm volatile(
                        "mma.sync.aligned.m16n8k8.row.col.f32.tf32.tf32.f32 "
                        "{%0,%1,%2,%3}, {%4,%5,%6,%7}, {%8,%9}, {%0,%1,%2,%3};"
                        : "+f"(acc[mi][ni][0]), "+f"(acc[mi][ni][1]),
                          "+f"(acc[mi][ni][2]), "+f"(acc[mi][ni][3])
                        : "r"(a[mi][0]), "r"(a[mi][1]), "r"(a[mi][2]), "r"(a[mi][3]),
                          "r"(bf[ni][0]), "r"(bf[ni][1]));
                }
        }

        __syncthreads();   // previous epilogue done reading staging
        {
            const int gg  = lane >> 2;
            const int tt4 = lane & 3;
#pragma unroll
            for (int mi = 0; mi < 2; mi++) {
#pragma unroll
                for (int ni = 0; ni < 3; ni++) {
                    int row = warpM*32 + mi*16 + gg;
                    int col = warpN*24 + ni*8 + tt4*2;
                    *(__half2*)&st[row*ST_PITCH + col] =
                        __floats2half2_rn(acc[mi][ni][0], acc[mi][ni][1]);
                    *(__half2*)&st[(row+8)*ST_PITCH + col] =
                        __floats2half2_rn(acc[mi][ni][2], acc[mi][ni][3]);
                }
            }
        }
        __syncthreads();

        // per-vertex state (loaded AFTER acc drained; L1-hot for mt>0)
        if (valid) {
            float hT[2][3], hts[2][3], huy[2], hwx[2], hw8[2][NB];
            int hx0[2], hx1[2];
#pragma unroll
            for (int u = 0; u < 2; u++) {
                const int v = vp + u;
#pragma unroll
                for (int c = 0; c < 3; c++) { hT[u][c] = T[v*3+c]; hts[u][c] = ts[v*3+c]; }
#pragma unroll
                for (int n = 0; n < NB; n++) hw8[u][n] = W[n*NV + v];
                float ux = uvgrid[v*2+0];
                huy[u] = uvgrid[v*2+1];
                float x = fminf(fmaxf(ux * 255.0f, 0.0f), 255.0f);
                hx0[u] = (int)floorf(x);
                hx1[u] = min(hx0[u] + 1, 255);
                hwx[u] = x - (float)hx0[u];
            }

            // epilogue: 4 rows x 2 vertices per thread
#pragma unroll
            for (int i = 0; i < 4; i++) {
                const int row = rgrp + i*16;
                const int b = Mbase + row;
                const float tb = tau[b];
                const float al = alpha[b];

                // 6 staged halves for the vertex pair: 3 LDS.32
                const __half* sp = st + row*ST_PITCH + vl2*6;
                float2 f0 = __half22float2(*(const __half2*)(sp + 0));
                float2 f1 = __half22float2(*(const __half2*)(sp + 2));
                float2 f2 = __half22float2(*(const __half2*)(sp + 4));
                float cc[6] = {f0.x, f0.y, f1.x, f1.y, f2.x, f2.y};

                float px[2], py[2], pz[2], ox[2], oy[2], oz[2];
#pragma unroll
                for (int u = 0; u < 2; u++) {
                    float y = fminf(fmaxf((huy[u] + tb) * 255.0f, 0.0f), 255.0f);
                    int y0 = (int)floorf(y);
                    int y1 = min(y0 + 1, 255);
                    float wy = y - (float)y0;
                    float v00 = L[y0*256 + hx0[u]], v01 = L[y0*256 + hx1[u]];
                    float v10 = L[y1*256 + hx0[u]], v11 = L[y1*256 + hx1[u]];
                    float wx = hwx[u];
                    float dist = (v00*(1.0f-wx) + v01*wx)*(1.0f-wy)
                               + (v10*(1.0f-wx) + v11*wx)*wy;
                    float s = al * dist;

                    px[u] = cc[u*3+0] + hT[u][0] + s*hts[u][0];
                    py[u] = cc[u*3+1] + hT[u][1] + s*hts[u][1];
                    pz[u] = cc[u*3+2] + hT[u][2] + s*hts[u][2];
                    ox[u] = 0.0f; oy[u] = 0.0f; oz[u] = 0.0f;
                }

                const float4* Gb = (const float4*)(g_bone + b*(NB*12));
#pragma unroll
                for (int n = 0; n < NB; n++) {
                    float4 g0 = Gb[n*3 + 0];   // shared by both vertices
                    float4 g1 = Gb[n*3 + 1];
                    float4 g2 = Gb[n*3 + 2];
#pragma unroll
                    for (int u = 0; u < 2; u++) {
                        float wn = hw8[u][n];
                        ox[u] = fmaf(wn, fmaf(g0.x, px[u], fmaf(g0.y, py[u], fmaf(g0.z, pz[u], g0.w))), ox[u]);
                        oy[u] = fmaf(wn, fmaf(g1.x, px[u], fmaf(g1.y, py[u], fmaf(g1.z, pz[u], g1.w))), oy[u]);
                        oz[u] = fmaf(wn, fmaf(g2.x, px[u], fmaf(g2.y, py[u], fmaf(g2.z, pz[u], g2.w))), oz[u]);
                    }
                }

                size_t base = (size_t)b * NV3 + (size_t)vp * 3;   // even offset
                *(float2*)&out[base + 0] = make_float2(ox[0], oy[0]);
                *(float2*)&out[base + 2] = make_float2(oz[0], ox[1]);
                *(float2*)&out[base + 4] = make_float2(oy[1], oz[1]);
            }
        }
    }
}

extern "C" void kernel_launch(void* const* d_in, const int* in_sizes, int n_in,
                              void* d_out, int out_size) {
    const float* theta  = (const float*)d_in[0];
    const float* tau    = (const float*)d_in[1];
    const float* alpha  = (const float*)d_in[2];
    const float* bsw    = (const float*)d_in[3];
    const float* W      = (const float*)d_in[4];
    const float* T      = (const float*)d_in[5];
    const float* P      = (const float*)d_in[6];
    const float* L      = (const float*)d_in[7];
    const float* ts     = (const float*)d_in[8];
    const float* L2P    = (const float*)d_in[9];
    const float* E      = (const float*)d_in[10];
    const float* uvgrid = (const float*)d_in[11];
    float* out = (float*)d_out;

    cudaFuncSetAttribute(fused_kernel,
                         cudaFuncAttributeMaxDynamicSharedMemorySize, SMEM_BYTES);

    prep_kernel<<<BATCH, 64>>>(theta, bsw, L2P);

    fused_kernel<<<NBLKS, 256, SMEM_BYTES>>>(P, E, T, W, ts, uvgrid, L, tau,
                                             alpha, out);
}

// round 12
// speedup vs baseline: 1.1955x; 1.1349x over previous
#include <cuda_runtime.h>
#include <cuda_bf16.h>
#include <cuda_fp16.h>
#include <math.h>
#include <stdint.h>

#define NB 8
#define BATCH 256
#define NV 14062
#define NV3 (NV*3)          // 42186
#define KD 120              // 63 pose-corr + 55 bsw + 2 zero pad (T excluded)
#define NTILE 96            // comps per block = 32 vertices exactly
#define VTILE 32
#define MTILE 64            // batches per M-tile iteration
#define NBLKS ((NV3 + NTILE - 1) / NTILE)   // 440
#define ST_PITCH 104        // staging row pitch in halves
#define DPITCH 14080        // dist row pitch (floats, 64-mult)

#define SB_WORDS (15*12*66)                  // 11880 (full-K B frags)
#define ST_BYTES (MTILE*ST_PITCH*2)          // 13312 (fp16 staging)
#define SMEM_BYTES (SB_WORDS*4 + ST_BYTES)   // 60832

// scratch (allocation-free requirement -> device globals)
__device__ __align__(16) uint32_t g_coefA[BATCH * KD];   // tf32 bits, A-frag order
__device__ __align__(16) float    g_bone[BATCH * NB * 12];
__device__ __align__(16) float    g_LT[256 * 256];       // transposed L
__device__ __align__(16) float    g_vert[14080 * 16];    // packed per-vertex consts
__device__ __align__(16) float    g_dist[(size_t)BATCH * DPITCH]; // alpha*dist

struct Aff { float r[9]; float t[3]; };

__device__ __forceinline__ Aff amul(const Aff& A, const Aff& B) {
    Aff C;
#pragma unroll
    for (int i = 0; i < 3; i++) {
#pragma unroll
        for (int j = 0; j < 3; j++)
            C.r[i*3+j] = A.r[i*3+0]*B.r[0*3+j] + A.r[i*3+1]*B.r[1*3+j] + A.r[i*3+2]*B.r[2*3+j];
        C.t[i] = A.r[i*3+0]*B.t[0] + A.r[i*3+1]*B.t[1] + A.r[i*3+2]*B.t[2] + A.t[i];
    }
    return C;
}

__device__ __forceinline__ Aff ainv_rigid(const Aff& A) {
    Aff C;
#pragma unroll
    for (int i = 0; i < 3; i++)
#pragma unroll
        for (int j = 0; j < 3; j++)
            C.r[i*3+j] = A.r[j*3+i];
#pragma unroll
    for (int i = 0; i < 3; i++)
        C.t[i] = -(C.r[i*3+0]*A.t[0] + C.r[i*3+1]*A.t[1] + C.r[i*3+2]*A.t[2]);
    return C;
}

__device__ __forceinline__ void rodrigues(const float* rv, float* R) {
    float x = rv[0], y = rv[1], z = rv[2];
    float d = x*x + y*y + z*z + 1e-12f;
    float ang = sqrtf(d);
    float inv = 1.0f / ang;
    float kx = x*inv, ky = y*inv, kz = z*inv;
    float s = sinf(ang), c = cosf(ang);
    float kk = kx*kx + ky*ky + kz*kz;
    float oc = 1.0f - c;
    R[0] = 1.0f + oc*(kx*kx - kk);
    R[1] = -s*kz + oc*(kx*ky);
    R[2] =  s*ky + oc*(kx*kz);
    R[3] =  s*kz + oc*(ky*kx);
    R[4] = 1.0f + oc*(ky*ky - kk);
    R[5] = -s*kx + oc*(ky*kz);
    R[6] = -s*ky + oc*(kz*kx);
    R[7] =  s*kx + oc*(kz*ky);
    R[8] = 1.0f + oc*(kz*kz - kk);
}

__device__ __forceinline__ uint32_t to_tf32(float f) {
    uint32_t u;
    asm("cvt.rna.tf32.f32 %0, %1;" : "=r"(u) : "f"(f));
    return u;
}

// write coef value k for batch b into m16n8k8 A-fragment-ordered g_coefA
__device__ __forceinline__ void store_coef(int b, int k, float v) {
    int b64  = b >> 6;
    int mblk = (b >> 4) & 3;
    int r    = b & 15;
    int g    = r & 7;
    int hi   = r >> 3;
    int k8 = k >> 3, t = k & 7, tig = t & 3, j2 = t >> 2;
    int lane = g*4 + tig;
    int reg  = j2*2 + hi;
    g_coefA[(((b64*15 + k8)*4 + mblk)*32 + lane)*4 + reg] = to_tf32(v);
}

// Merged prep: one block per batch.
__global__ void prep_kernel(const float* __restrict__ theta,
                            const float* __restrict__ bsw,
                            const float* __restrict__ L2P) {
    __shared__ float sR[NB * 9];
    const int b = blockIdx.x;
    const int t = threadIdx.x;
    if (t < 8) {
        float R[9];
        rodrigues(theta + (b*NB + t)*3, R);
#pragma unroll
        for (int i = 0; i < 9; i++) sR[t*9 + i] = R[i];
        if (t >= 1) {
#pragma unroll
            for (int i = 0; i < 3; i++)
#pragma unroll
                for (int j = 0; j < 3; j++)
                    store_coef(b, (t-1)*9 + i*3 + j, R[i*3+j] - (i == j ? 1.0f : 0.0f));
        }
    } else if (t < 63) {
        int j = t - 8;
        store_coef(b, 63 + j, bsw[b*55 + j]);
    }
    __syncthreads();

    if (t == 0) {
        Aff M, rest;
#pragma unroll
        for (int n = 0; n < NB; n++) {
            Aff l2p;
#pragma unroll
            for (int i = 0; i < 3; i++) {
#pragma unroll
                for (int j = 0; j < 3; j++) l2p.r[i*3+j] = L2P[n*16 + i*4 + j];
                l2p.t[i] = L2P[n*16 + i*4 + 3];
            }
            Aff loc;
#pragma unroll
            for (int i = 0; i < 9; i++) loc.r[i] = sR[n*9 + i];
            loc.t[0] = loc.t[1] = loc.t[2] = 0.0f;

            Aff An = amul(l2p, loc);
            M    = (n == 0) ? An  : amul(M, An);
            rest = (n == 0) ? l2p : amul(rest, l2p);

            Aff w2l = ainv_rigid(rest);
            Aff G = amul(M, w2l);

            float* gp = g_bone + b*(NB*12) + n*12;
#pragma unroll
            for (int i = 0; i < 3; i++) {
                gp[i*4+0] = G.r[i*3+0];
                gp[i*4+1] = G.r[i*3+1];
                gp[i*4+2] = G.r[i*3+2];
                gp[i*4+3] = G.t[i];
            }
        }
    }
}

// transpose L (256x256): LT[x][y] = L[y][x]; reads coalesced.
__global__ void transpose_kernel(const float* __restrict__ L) {
    int y = blockIdx.x;
    int x = threadIdx.x;
    g_LT[x*256 + y] = L[y*256 + x];
}

// dist pass + per-vertex constant packing.
// Block = 32 vertices; warp = 32 batches (lane=batch), loops the 32 verts.
// Gathers hit transposed L so the 32 lanes (y spread ~ +-25px by tau) touch
// only a few lines. Output g_dist[b][v] = alpha[b] * bilinear(L), staged via
// smem transpose for coalesced stores. Also packs g_vert[v][16] = {T,ts,w8}.
__global__ __launch_bounds__(256)
void dist_kernel(const float* __restrict__ uvgrid,
                 const float* __restrict__ tau,
                 const float* __restrict__ alpha,
                 const float* __restrict__ T,
                 const float* __restrict__ ts,
                 const float* __restrict__ W) {
    __shared__ float sd[8][32*33];   // 33792 B
    const int tid  = threadIdx.x;
    const int w    = tid >> 5;
    const int lane = tid & 31;
    const int v0   = blockIdx.x * VTILE;

    // pack g_vert for these 32 vertices
    for (int idx = tid; idx < 32*16; idx += 256) {
        int u = idx >> 4, slot = idx & 15;
        int v = v0 + u;
        if (v < NV) {
            float val = 0.0f;
            if (slot < 3)                    val = T[v*3 + slot];
            else if (slot >= 4 && slot < 7)  val = ts[v*3 + (slot-4)];
            else if (slot >= 8)              val = W[(slot-8)*NV + v];
            g_vert[v*16 + slot] = val;
        }
    }

    const int b  = w*32 + lane;
    const float tb = tau[b];
    const float al = alpha[b];
    float* sdw = sd[w];

    for (int u = 0; u < 32; u++) {
        int v = v0 + u;
        float val = 0.0f;
        if (v < NV) {
            float ux = uvgrid[v*2+0];     // broadcast
            float uy = uvgrid[v*2+1];
            float x = fminf(fmaxf(ux * 255.0f, 0.0f), 255.0f);
            int x0 = (int)floorf(x);
            int x1 = min(x0 + 1, 255);
            float wx = x - (float)x0;
            float y = fminf(fmaxf((uy + tb) * 255.0f, 0.0f), 255.0f);
            int y0 = (int)floorf(y);
            int y1 = min(y0 + 1, 255);
            float wy = y - (float)y0;
            float v00 = g_LT[x0*256 + y0], v01 = g_LT[x1*256 + y0];
            float v10 = g_LT[x0*256 + y1], v11 = g_LT[x1*256 + y1];
            val = al * ((v00*(1.0f-wx) + v01*wx)*(1.0f-wy)
                      + (v10*(1.0f-wx) + v11*wx)*wy);
        }
        sdw[u*33 + lane] = val;
    }
    __syncwarp();

    // coalesced write-out: 8 iters, each writes 4 batch-rows x 32 verts
#pragma unroll
    for (int j = 0; j < 8; j++) {
        int br = j*4 + (lane >> 3);       // batch row within warp
        int vc = (lane & 7) * 4;          // vert column (float4)
        float4 val = make_float4(sdw[(vc+0)*33 + br], sdw[(vc+1)*33 + br],
                                 sdw[(vc+2)*33 + br], sdw[(vc+3)*33 + br]);
        *(float4*)&g_dist[(size_t)(w*32 + br)*DPITCH + v0 + vc] = val;
    }
}

// Fused tf32 GEMM + epilogue, B-stationary, 3 CTAs/SM, fp16 staging.
// Epilogue: 2 verts x 4 rows per thread; per-vertex state = 8 LDG.128 from
// packed g_vert (reloaded per M-tile, after acc drain); larynx term = one
// coalesced LDG.64 from precomputed g_dist (alpha folded in).
__global__ __launch_bounds__(256, 3)
void fused_kernel(const float* __restrict__ P,
                  const float* __restrict__ E,
                  float* __restrict__ out) {
    extern __shared__ __align__(16) char smem_raw[];
    uint32_t* sB = (uint32_t*)smem_raw;
    __half*   st = (__half*)(sB + SB_WORDS);

    const int tid   = threadIdx.x;
    const int lane  = tid & 31;
    const int wid   = tid >> 5;
    const int warpM = wid >> 2;      // 0..1
    const int warpN = wid & 3;       // 0..3
    const int cbase = blockIdx.x * NTILE;
    const int vbase = blockIdx.x * VTILE;

    // ---- fill full-K B tile [120 x 96] in fragment order (once) ----
    for (int idx = tid; idx < KD*NTILE; idx += 256) {
        int kl = idx / NTILE;
        int cl = idx - kl*NTILE;
        int c  = cbase + cl;
        float v = 0.0f;
        if (c < NV3) {
            if (kl < 63)       v = P[(size_t)(kl+9)*NV3 + c];
            else if (kl < 118) v = E[(size_t)(kl-63)*NV3 + c];
        }
        int k8 = kl >> 3, t = kl & 7, tig = t & 3, j = t >> 2;
        int nblk = cl >> 3, gg = cl & 7;
        sB[k8*(12*66) + nblk*66 + (gg*4 + tig)*2 + j] = to_tf32(v);
    }

    // epilogue thread mapping: 2 adjacent vertices x 4 rows
    const int vl2  = tid & 15;
    const int rgrp = tid >> 4;
    const int vp   = vbase + vl2*2;
    const bool valid = (vp < NV);

    __syncthreads();

    // ---- M-tile loop ----
    for (int mt = 0; mt < 4; mt++) {
        const uint32_t* Ag = g_coefA + mt*(MTILE*KD);
        const int Mbase = mt * MTILE;

        float acc[2][3][4];
#pragma unroll
        for (int mi = 0; mi < 2; mi++)
#pragma unroll
            for (int ni = 0; ni < 3; ni++)
#pragma unroll
                for (int qq = 0; qq < 4; qq++) acc[mi][ni][qq] = 0.0f;

#pragma unroll
        for (int k8 = 0; k8 < 15; k8++) {
            uint32_t a[2][4];
#pragma unroll
            for (int mi = 0; mi < 2; mi++) {
                uint4 av = *(const uint4*)&Ag[((k8*4 + warpM*2 + mi)*32 + lane)*4];
                a[mi][0] = av.x; a[mi][1] = av.y; a[mi][2] = av.z; a[mi][3] = av.w;
            }
            uint32_t bf[3][2];
#pragma unroll
            for (int ni = 0; ni < 3; ni++) {
                uint2 bv = *(const uint2*)&sB[k8*(12*66) + (warpN*3 + ni)*66 + lane*2];
                bf[ni][0] = bv.x; bf[ni][1] = bv.y;
            }
#pragma unroll
            for (int mi = 0; mi < 2; mi++)
#pragma unroll
                for (int ni = 0; ni < 3; ni++) {
                    asm volatile(
                        "mma.sync.aligned.m16n8k8.row.col.f32.tf32.tf32.f32 "
                        "{%0,%1,%2,%3}, {%4,%5,%6,%7}, {%8,%9}, {%0,%1,%2,%3};"
                        : "+f"(acc[mi][ni][0]), "+f"(acc[mi][ni][1]),
                          "+f"(acc[mi][ni][2]), "+f"(acc[mi][ni][3])
                        : "r"(a[mi][0]), "r"(a[mi][1]), "r"(a[mi][2]), "r"(a[mi][3]),
                          "r"(bf[ni][0]), "r"(bf[ni][1]));
                }
        }

        __syncthreads();   // previous epilogue done reading staging
        {
            const int gg  = lane >> 2;
            const int tt4 = lane & 3;
#pragma unroll
            for (int mi = 0; mi < 2; mi++) {
#pragma unroll
                for (int ni = 0; ni < 3; ni++) {
                    int row = warpM*32 + mi*16 + gg;
                    int col = warpN*24 + ni*8 + tt4*2;
                    *(__half2*)&st[row*ST_PITCH + col] =
                        __floats2half2_rn(acc[mi][ni][0], acc[mi][ni][1]);
                    *(__half2*)&st[(row+8)*ST_PITCH + col] =
                        __floats2half2_rn(acc[mi][ni][2], acc[mi][ni][3]);
                }
            }
        }
        __syncthreads();

        if (valid) {
            // packed per-vertex state: 4 LDG.128 per vertex
            float hT[2][3], hts[2][3], hw8[2][NB];
#pragma unroll
            for (int u = 0; u < 2; u++) {
                const float4* gv = (const float4*)&g_vert[(vp+u)*16];
                float4 a0 = gv[0];   // T
                float4 a1 = gv[1];   // ts
                float4 a2 = gv[2];   // w0-3
                float4 a3 = gv[3];   // w4-7
                hT[u][0] = a0.x; hT[u][1] = a0.y; hT[u][2] = a0.z;
                hts[u][0] = a1.x; hts[u][1] = a1.y; hts[u][2] = a1.z;
                hw8[u][0] = a2.x; hw8[u][1] = a2.y; hw8[u][2] = a2.z; hw8[u][3] = a2.w;
                hw8[u][4] = a3.x; hw8[u][5] = a3.y; hw8[u][6] = a3.z; hw8[u][7] = a3.w;
            }

            // epilogue: 4 rows x 2 vertices per thread
#pragma unroll
            for (int i = 0; i < 4; i++) {
                const int row = rgrp + i*16;
                const int b = Mbase + row;

                // precomputed alpha*dist for the vertex pair (coalesced)
                float2 dv = *(const float2*)&g_dist[(size_t)b*DPITCH + vp];

                // 6 staged halves for the vertex pair
                const __half* sp = st + row*ST_PITCH + vl2*6;
                float2 f0 = __half22float2(*(const __half2*)(sp + 0));
                float2 f1 = __half22float2(*(const __half2*)(sp + 2));
                float2 f2 = __half22float2(*(const __half2*)(sp + 4));
                float cc[6] = {f0.x, f0.y, f1.x, f1.y, f2.x, f2.y};

                float px[2], py[2], pz[2], ox[2], oy[2], oz[2];
#pragma unroll
                for (int u = 0; u < 2; u++) {
                    float s = (u == 0) ? dv.x : dv.y;
                    px[u] = cc[u*3+0] + hT[u][0] + s*hts[u][0];
                    py[u] = cc[u*3+1] + hT[u][1] + s*hts[u][1];
                    pz[u] = cc[u*3+2] + hT[u][2] + s*hts[u][2];
                    ox[u] = 0.0f; oy[u] = 0.0f; oz[u] = 0.0f;
                }

                const float4* Gb = (const float4*)(g_bone + b*(NB*12));
#pragma unroll
                for (int n = 0; n < NB; n++) {
                    float4 g0 = Gb[n*3 + 0];   // shared by both vertices
                    float4 g1 = Gb[n*3 + 1];
                    float4 g2 = Gb[n*3 + 2];
#pragma unroll
                    for (int u = 0; u < 2; u++) {
                        float wn = hw8[u][n];
                        ox[u] = fmaf(wn, fmaf(g0.x, px[u], fmaf(g0.y, py[u], fmaf(g0.z, pz[u], g0.w))), ox[u]);
                        oy[u] = fmaf(wn, fmaf(g1.x, px[u], fmaf(g1.y, py[u], fmaf(g1.z, pz[u], g1.w))), oy[u]);
                        oz[u] = fmaf(wn, fmaf(g2.x, px[u], fmaf(g2.y, py[u], fmaf(g2.z, pz[u], g2.w))), oz[u]);
                    }
                }

                size_t base = (size_t)b * NV3 + (size_t)vp * 3;   // even offset
                *(float2*)&out[base + 0] = make_float2(ox[0], oy[0]);
                *(float2*)&out[base + 2] = make_float2(oz[0], ox[1]);
                *(float2*)&out[base + 4] = make_float2(oy[1], oz[1]);
            }
        }
    }
}

extern "C" void kernel_launch(void* const* d_in, const int* in_sizes, int n_in,
                              void* d_out, int out_size) {
    const float* theta  = (const float*)d_in[0];
    const float* tau    = (const float*)d_in[1];
    const float* alpha  = (const float*)d_in[2];
    const float* bsw    = (const float*)d_in[3];
    const float* W      = (const float*)d_in[4];
    const float* T      = (const float*)d_in[5];
    const float* P      = (const float*)d_in[6];
    const float* L      = (const float*)d_in[7];
    const float* ts     = (const float*)d_in[8];
    const float* L2P    = (const float*)d_in[9];
    const float* E      = (const float*)d_in[10];
    const float* uvgrid = (const float*)d_in[11];
    float* out = (float*)d_out;

    cudaFuncSetAttribute(fused_kernel,
                         cudaFuncAttributeMaxDynamicSharedMemorySize, SMEM_BYTES);

    prep_kernel<<<BATCH, 64>>>(theta, bsw, L2P);
    transpose_kernel<<<256, 256>>>(L);
    dist_kernel<<<NBLKS, 256>>>(uvgrid, tau, alpha, T, ts, W);

    fused_kernel<<<NBLKS, 256, SMEM_BYTES>>>(P, E, out);
}